// round 9
// baseline (speedup 1.0000x reference)
#include <cuda_runtime.h>

// B-spline layer, ONE kernel with in-kernel producer/consumer fold.
// out[b,f] = ((q3*u+q2)*u+q1)*u + q0, u = 55x - ii, ii = floor(55x) in [0,54],
// q_d[ii,f] = sum_r P[ii][r][d] * C[ii+3+r,f]  (bias folded into q0).
// P = Cox-de Boor basis polynomial coefficients in local coord u, computed on
// the HOST in double (knot-only, deterministic), passed in the const bank.
//
// Grid = 512 blocks (1D), 512 threads. tile = bid & 7 (feature tile),
// xchunk = bid >> 3 (64 batch rows). Blocks 0..7 (xchunk==0, wave-1 residents)
// fold tile -> g_tab + own smem, release flag. Others prefetch X, acquire-spin
// on flag, copy tile from L2, run hot loop. Last block resets flags/counter
// (all state returns to 0 within the call -> deterministic across replays).

#define NF 256
#define NBATCH 4096
#define NII 55
#define NTILES 8
#define NBLOCKS 512
#define NTHREADS 512
#define TABN (NII * 32)          // 1760 float4 per tile

struct PTab { float p[NII][4][4]; };

__device__ float4 g_tab[NTILES * TABN];   // 225 KB, L2-resident
__device__ int    g_ready[NTILES];        // zero-init; reset to 0 each call
__device__ int    g_done;                 // zero-init; reset to 0 each call

// ---------------- host-side knot/coefficient math (double) ----------------
static double knotD_h(int idx) {
    if (idx < 6)  return -0.002 + 0.0005 * (double)(idx - 3);
    if (idx > 61) return 1.001  + 0.0005 * (double)(idx - 62);
    return (double)(idx - 6) / 55.0;
}

static void make_ptab(PTab& T) {
    for (int ii = 0; ii < NII; ++ii) {
        const int j = ii + 6;
        double P[4][4] = {};
        P[0][0] = 1.0;
        const double x0 = (double)ii / 55.0;
        const double bs = 1.0 / 55.0;   // x = x0 + bs*u
        for (int k = 1; k <= 3; ++k) {
            double Q[4][4] = {};
            for (int r = 0; r <= k; ++r) {
                const int i = j - k + r;
                if (r >= 1) {
                    const double inv = 1.0 / (knotD_h(i + k) - knotD_h(i));
                    const double a = (x0 - knotD_h(i)) * inv;
                    const double b = bs * inv;
                    for (int d = 0; d < 4; ++d) {
                        Q[r][d] += a * P[r - 1][d];
                        if (d > 0) Q[r][d] += b * P[r - 1][d - 1];
                    }
                }
                if (r <= k - 1) {
                    const double inv = 1.0 / (knotD_h(i + k + 1) - knotD_h(i + 1));
                    const double a = (knotD_h(i + k + 1) - x0) * inv;
                    const double b = -bs * inv;
                    for (int d = 0; d < 4; ++d) {
                        Q[r][d] += a * P[r][d];
                        if (d > 0) Q[r][d] += b * P[r][d - 1];
                    }
                }
            }
            for (int r = 0; r < 4; ++r)
                for (int d = 0; d < 4; ++d) P[r][d] = Q[r][d];
        }
        for (int r = 0; r < 4; ++r)
            for (int d = 0; d < 4; ++d) T.p[ii][r][d] = (float)P[r][d];
    }
}

// ------------------------- acquire/release helpers -------------------------
__device__ __forceinline__ int ld_acquire_gpu(const int* p) {
    int v;
    asm volatile("ld.acquire.gpu.global.b32 %0, [%1];" : "=r"(v) : "l"(p) : "memory");
    return v;
}
__device__ __forceinline__ void st_release_gpu(int* p, int v) {
    asm volatile("st.release.gpu.global.b32 [%0], %1;" :: "l"(p), "r"(v) : "memory");
}

// --------------------------------- kernel ---------------------------------
__global__ __launch_bounds__(NTHREADS, 4) void BSL_25898652795515_kernel(
    const PTab T,                     // 3.5 KB const bank
    const float* __restrict__ X,      // (4096, 256)
    const float* __restrict__ C,      // (64, 256)
    const float* __restrict__ bias,   // (256,)
    float* __restrict__ out)          // (4096, 256)
{
    __shared__ float4 sT[TABN];       // 28 KB folded coefficient tile

    const int bid    = blockIdx.x;
    const int tile   = bid & 7;       // feature tile 0..7
    const int xchunk = bid >> 3;      // 0..63
    const int row0   = xchunk * 64;
    const int tid    = threadIdx.x;
    const int lane   = tid & 31;
    const int wrp    = tid >> 5;      // 0..15
    const int f0     = tile * 32;
    const int f      = f0 + lane;

    // Prefetch X rows (DRAM latency overlaps fold/spin).
    float xv[4];
    #pragma unroll
    for (int it = 0; it < 4; ++it)
        xv[it] = X[(row0 + it * 16 + wrp) * NF + f];

    if (xchunk == 0) {
        // ---- producer: fold tile into smem AND g_tab ----
        // ii = o>>5 warp-uniform -> P reads on the uniform const port;
        // 4 independent coalesced LDGs per element.
        for (int o = tid; o < TABN; o += NTHREADS) {
            const int ii = o >> 5;
            const int ln = o & 31;
            const float c0 = __ldg(&C[(ii + 3) * NF + f0 + ln]);
            const float c1 = __ldg(&C[(ii + 4) * NF + f0 + ln]);
            const float c2 = __ldg(&C[(ii + 5) * NF + f0 + ln]);
            const float c3 = __ldg(&C[(ii + 6) * NF + f0 + ln]);
            float4 q;
            q.x = fmaf(T.p[ii][0][0], c0, fmaf(T.p[ii][1][0], c1,
                  fmaf(T.p[ii][2][0], c2, fmaf(T.p[ii][3][0], c3,
                  __ldg(&bias[f0 + ln])))));
            q.y = fmaf(T.p[ii][0][1], c0, fmaf(T.p[ii][1][1], c1,
                  fmaf(T.p[ii][2][1], c2, T.p[ii][3][1] * c3)));
            q.z = fmaf(T.p[ii][0][2], c0, fmaf(T.p[ii][1][2], c1,
                  fmaf(T.p[ii][2][2], c2, T.p[ii][3][2] * c3)));
            q.w = fmaf(T.p[ii][0][3], c0, fmaf(T.p[ii][1][3], c1,
                  fmaf(T.p[ii][2][3], c2, T.p[ii][3][3] * c3)));
            sT[o] = q;
            g_tab[tile * TABN + o] = q;
        }
        __threadfence();              // make g_tab stores GPU-visible
        __syncthreads();              // all threads' stores done (and sT ready)
        if (tid == 0) st_release_gpu(&g_ready[tile], 1);
    } else {
        // ---- consumer: wait for producer, then copy tile from L2 ----
        while (ld_acquire_gpu(&g_ready[tile]) == 0) __nanosleep(64);
        for (int idx = tid; idx < TABN; idx += NTHREADS)
            sT[idx] = g_tab[tile * TABN + idx];
        __syncthreads();
    }

    // ---- hot loop: conflict-free LDS.128 (ii stride 512 B == 0 mod banks) --
    #pragma unroll
    for (int it = 0; it < 4; ++it) {
        const float xs = xv[it] * 55.0f;
        int ii = (int)xs;             // x >= 0 -> trunc == floor
        ii = min(ii, 54);
        const float u = xs - (float)ii;
        const float4 c = sT[ii * 32 + lane];
        out[(row0 + it * 16 + wrp) * NF + f] =
            fmaf(fmaf(fmaf(c.w, u, c.z), u, c.y), u, c.x);
    }

    // ---- epilogue: last block resets flags/counter for the next replay ----
    // (A block only increments after its own spin has passed, so the reset
    //  can never race a pending reader within this call.)
    if (tid == 0) {
        const int old = atomicAdd(&g_done, 1);
        if (old == NBLOCKS - 1) {
            g_done = 0;
            #pragma unroll
            for (int t = 0; t < NTILES; ++t) g_ready[t] = 0;
        }
    }
}

extern "C" void kernel_launch(void* const* d_in, const int* in_sizes, int n_in,
                              void* d_out, int out_size) {
    const float* x    = (const float*)d_in[0];   // (4096, 256)
    const float* ctrl = (const float*)d_in[1];   // (64, 256)
    const float* bias = (const float*)d_in[2];   // (256,)
    float* out = (float*)d_out;

    PTab T;
    make_ptab(T);   // host double math, knot-only, deterministic

    BSL_25898652795515_kernel<<<NBLOCKS, NTHREADS>>>(T, x, ctrl, bias, out);
}

// round 11
// speedup vs baseline: 1.9815x; 1.9815x over previous
#include <cuda_runtime.h>

// B-spline layer, single fused kernel.
// out[b,f] = ((q3*u+q2)*u+q1)*u + q0,  u = 55x - ii, ii = floor(55x) in [0,54],
// q_d[ii,f] = sum_r P[ii][r][d] * C[ii+3+r, f]   (bias folded into q0).
// P = Cox-de Boor basis polynomial coefficients in local coord u, computed on
// the HOST in double (knot-only, deterministic), passed in the const bank.
//
// Cvt-free interval math (fixed from R10): m = fmaf(x,55,2^23) stays in
// [2^23, 2^23+55] where fp32 spacing is exactly 1, so mantissa(m) = n =
// round(55x). Then u0 = fmaf(x,55,-n) in [-0.5,0.5] and the branchless fixup
// ii = n - (u0<0), u = u0 + (u0<0) gives floor semantics. No clamp needed:
// x in [0,1) => ii in [0,54].
//
// Grid 256 blocks x 512 thr: each block folds its 28 KB tile once (direct from
// L2, no staging, one sync), then streams 128 batch rows (8-deep X prefetch).

#define NF 256
#define NBATCH 4096
#define NII 55
#define NTHREADS 512
#define ROWS_PER_BLOCK 128
#define TABN (NII * 32)           // 1760 float4

struct PTab { float p[NII][4][4]; };

// ---------------- host-side knot/coefficient math (double) ----------------
static double knotD_h(int idx) {
    if (idx < 6)  return -0.002 + 0.0005 * (double)(idx - 3);
    if (idx > 61) return 1.001  + 0.0005 * (double)(idx - 62);
    return (double)(idx - 6) / 55.0;
}

static void make_ptab(PTab& T) {
    for (int ii = 0; ii < NII; ++ii) {
        const int j = ii + 6;
        double P[4][4] = {};
        P[0][0] = 1.0;
        const double x0 = (double)ii / 55.0;
        const double bs = 1.0 / 55.0;   // x = x0 + bs*u
        for (int k = 1; k <= 3; ++k) {
            double Q[4][4] = {};
            for (int r = 0; r <= k; ++r) {
                const int i = j - k + r;
                if (r >= 1) {
                    const double inv = 1.0 / (knotD_h(i + k) - knotD_h(i));
                    const double a = (x0 - knotD_h(i)) * inv;
                    const double b = bs * inv;
                    for (int d = 0; d < 4; ++d) {
                        Q[r][d] += a * P[r - 1][d];
                        if (d > 0) Q[r][d] += b * P[r - 1][d - 1];
                    }
                }
                if (r <= k - 1) {
                    const double inv = 1.0 / (knotD_h(i + k + 1) - knotD_h(i + 1));
                    const double a = (knotD_h(i + k + 1) - x0) * inv;
                    const double b = -bs * inv;
                    for (int d = 0; d < 4; ++d) {
                        Q[r][d] += a * P[r][d];
                        if (d > 0) Q[r][d] += b * P[r][d - 1];
                    }
                }
            }
            for (int r = 0; r < 4; ++r)
                for (int d = 0; d < 4; ++d) P[r][d] = Q[r][d];
        }
        for (int r = 0; r < 4; ++r)
            for (int d = 0; d < 4; ++d) T.p[ii][r][d] = (float)P[r][d];
    }
}

// --------------------------------- kernel ---------------------------------
__global__ __launch_bounds__(NTHREADS) void BSL_25898652795515_kernel(
    const PTab T,                     // 3.5 KB const bank
    const float* __restrict__ X,      // (4096, 256)
    const float* __restrict__ C,      // (64, 256)
    const float* __restrict__ bias,   // (256,)
    float* __restrict__ out)          // (4096, 256)
{
    __shared__ float4 sT[TABN];       // 28 KB folded coefficient tile

    const int tile = blockIdx.y;      // feature tile 0..7
    const int f0   = tile * 32;
    const int row0 = blockIdx.x * ROWS_PER_BLOCK;
    const int tid  = threadIdx.x;
    const int lane = tid & 31;
    const int wrp  = tid >> 5;        // 0..15
    const int f    = f0 + lane;

    // ---- prefetch X rows (8-deep MLP; DRAM latency overlaps the fold) ----
    float xv[8];
    #pragma unroll
    for (int it = 0; it < 8; ++it)
        xv[it] = X[(row0 + it * 16 + wrp) * NF + f];

    // ---- fold (once per block), direct from L2, no staging ----
    // ii = o>>5 warp-uniform -> P reads on the uniform const port;
    // 4 independent coalesced LDGs per element.
    for (int o = tid; o < TABN; o += NTHREADS) {
        const int ii = o >> 5;
        const int ln = o & 31;
        const float c0 = __ldg(&C[(ii + 3) * NF + f0 + ln]);
        const float c1 = __ldg(&C[(ii + 4) * NF + f0 + ln]);
        const float c2 = __ldg(&C[(ii + 5) * NF + f0 + ln]);
        const float c3 = __ldg(&C[(ii + 6) * NF + f0 + ln]);
        float4 q;
        q.x = fmaf(T.p[ii][0][0], c0, fmaf(T.p[ii][1][0], c1,
              fmaf(T.p[ii][2][0], c2, fmaf(T.p[ii][3][0], c3,
              __ldg(&bias[f0 + ln])))));
        q.y = fmaf(T.p[ii][0][1], c0, fmaf(T.p[ii][1][1], c1,
              fmaf(T.p[ii][2][1], c2, T.p[ii][3][1] * c3)));
        q.z = fmaf(T.p[ii][0][2], c0, fmaf(T.p[ii][1][2], c1,
              fmaf(T.p[ii][2][2], c2, T.p[ii][3][2] * c3)));
        q.w = fmaf(T.p[ii][0][3], c0, fmaf(T.p[ii][1][3], c1,
              fmaf(T.p[ii][2][3], c2, T.p[ii][3][3] * c3)));
        sT[o] = q;
    }
    __syncthreads();

    // ---- hot loop: cvt-free ii/u (fixed), conflict-free LDS.128 ----
    const float MAGIC = 8388608.0f;   // 2^23: spacing 1 over [2^23, 2^23+55]
    #pragma unroll
    for (int it = 0; it < 8; ++it) {
        const float m   = fmaf(xv[it], 55.0f, MAGIC);     // 2^23 + round(55x)
        const int   n   = __float_as_int(m) & 0x7FFFFF;   // n = round(55x)
        const float nf  = m - MAGIC;                      // (float)n, exact
        const float u0  = fmaf(xv[it], 55.0f, -nf);       // 55x - n in [-0.5,0.5]
        const bool  neg = (u0 < 0.0f);
        const int   ii  = n - (neg ? 1 : 0);              // floor(55x), in [0,54]
        const float u   = u0 + (neg ? 1.0f : 0.0f);
        // LDS.128: bank16 = lane -> conflict-free (ii stride 512 B)
        const float4 c = sT[ii * 32 + lane];
        out[(row0 + it * 16 + wrp) * NF + f] =
            fmaf(fmaf(fmaf(c.w, u, c.z), u, c.y), u, c.x);
    }
}

extern "C" void kernel_launch(void* const* d_in, const int* in_sizes, int n_in,
                              void* d_out, int out_size) {
    const float* x    = (const float*)d_in[0];   // (4096, 256)
    const float* ctrl = (const float*)d_in[1];   // (64, 256)
    const float* bias = (const float*)d_in[2];   // (256,)
    float* out = (float*)d_out;

    PTab T;
    make_ptab(T);   // host double math, knot-only, deterministic

    dim3 grid(NBATCH / ROWS_PER_BLOCK, NF / 32);   // (32, 8) = 256 blocks
    BSL_25898652795515_kernel<<<grid, NTHREADS>>>(T, x, ctrl, bias, out);
}